// round 14
// baseline (speedup 1.0000x reference)
#include <cuda_runtime.h>
#include <math.h>

// Problem shape (fixed): B=2, S=8, N=2048, D=3
#define NPTS   2048
#define NSETS  16                    // B*S
#define PAD    16                    // sentinel entries each side (smem only)

// Main NN kernel geometry
#define TPB    128
#define QPB    128                   // queries per block (1 per thread)
#define CHUNKS (NPTS / QPB)          // 16
#define NBLK   (NSETS * 2 * CHUNKS)  // 512 blocks

// Sentinel: x-magnitude big enough to trigger the stop bound, small enough
// that k = w + q·x stays ~1e36 (never wins) without overflow.
#define SENT_X 1.0e18f
#define SENT_W 1.0e36f

// Sorted point sets: index = set*2 + which (0: X_v, 1: target), sorted ascending
// by .x field. Stored as {-2x, -2y, -2z, ||t||^2}.
__device__ float4 g_db[NSETS * 2][NPTS];

__device__ float g_loss_part[NBLK];
__device__ float g_cent_part[NBLK][3];
__device__ unsigned int g_ctr = 0;   // self-resetting completion counter

__device__ __forceinline__ float smooth_l1(float a, float b) {
    float d = fabsf(a - b);
    return (d < 1.0f) ? (0.5f * d * d) : (d - 0.5f);
}

// ---------------------------------------------------------------------------
// Kernel A: per (set, which), load points, sort by the -2x key in smem
// with a bitonic sort, write to g_db. 32 blocks x 256 threads.
// ---------------------------------------------------------------------------
__global__ __launch_bounds__(256)
void sort_kernel(const float* __restrict__ Xv, const float* __restrict__ Tv)
{
    const int blk   = blockIdx.x;          // 0..31
    const int set   = blk >> 1;
    const int which = blk & 1;             // 0: X_v, 1: target
    const float* __restrict__ src = (which ? Tv : Xv) + set * NPTS * 3;

    __shared__ float4 buf[NPTS];           // 32 KB

    for (int i = threadIdx.x; i < NPTS; i += 256) {
        float x = src[3 * i + 0];
        float y = src[3 * i + 1];
        float z = src[3 * i + 2];
        float n = x * x;
        n = fmaf(y, y, n);
        n = fmaf(z, z, n);
        buf[i] = make_float4(-2.0f * x, -2.0f * y, -2.0f * z, n);
    }
    __syncthreads();

    // Bitonic sort ascending by .x  (deterministic fixed schedule)
    for (int k = 2; k <= NPTS; k <<= 1) {
        for (int j = k >> 1; j > 0; j >>= 1) {
            for (int i = threadIdx.x; i < NPTS; i += 256) {
                int ixj = i ^ j;
                if (ixj > i) {
                    float4 a = buf[i];
                    float4 b = buf[ixj];
                    bool up = ((i & k) == 0);
                    if ((a.x > b.x) == up) { buf[i] = b; buf[ixj] = a; }
                }
            }
            __syncthreads();
        }
    }

    for (int i = threadIdx.x; i < NPTS; i += 256)
        g_db[blk][i] = buf[i];
}

// ---------------------------------------------------------------------------
// Kernel B: pruned NN search. Each thread owns one query: binary-search the
// sorted DB, expand outward in 8-candidate tiles, stop each side when the
// exact bound (x_t - x_q)^2 >= best d^2 holds OR the side is exhausted.
// ---------------------------------------------------------------------------
__global__ __launch_bounds__(TPB)
void nn_kernel(const float* __restrict__ w, float* __restrict__ out)
{
    const int tid   = threadIdx.x;
    const int blk   = blockIdx.x;
    const int set   = blk / (2 * CHUNKS);
    const int rem   = blk % (2 * CHUNKS);
    const int dir   = rem / CHUNKS;      // 0: queries=X_v, db=target ; 1: swapped
    const int chunk = rem % CHUNKS;

    const float4* __restrict__ qsrc = g_db[set * 2 + dir];
    const float4* __restrict__ dsrc = g_db[set * 2 + (1 - dir)];

    __shared__ float4 db[NPTS + 2 * PAD];   // ~32.5 KB
    __shared__ float4 red4[TPB];            // 2 KB
    __shared__ unsigned int is_last;

    for (int i = tid; i < NPTS; i += TPB)
        db[PAD + i] = dsrc[i];
    if (tid < PAD) {
        db[tid]              = make_float4(-SENT_X, 0.0f, 0.0f, SENT_W);
        db[NPTS + PAD + tid] = make_float4( SENT_X, 0.0f, 0.0f, SENT_W);
    }
    __syncthreads();

    // This thread's query (sorted order).
    const int qi = chunk * QPB + tid;
    const float4 qv = qsrc[qi];
    const float mxq = qv.x;                  // -2x_q  (search key space)
    const float qx = -0.5f * qv.x;
    const float qy = -0.5f * qv.y;
    const float qz = -0.5f * qv.z;
    const float p2 = qv.w;

    // Binary search: first index with db.x >= mxq.
    int lo = 0, hi = NPTS;
    while (lo < hi) {
        int mid = (lo + hi) >> 1;
        if (db[PAD + mid].x < mxq) lo = mid + 1; else hi = mid;
    }
    int r = PAD + lo;        // expand right: r, r+1, ...
    int l = PAD + lo - 1;    // expand left:  l, l-1, ...

    // best = min over scanned candidates of (d^2 - p2).
    float best = 3.0e38f;
    bool rdone = false, ldone = false;
    while (!(rdone && ldone)) {
        if (!rdone) {
#pragma unroll
            for (int u = 0; u < 8; u++) {
                float4 t = db[r + u];
                float k = fmaf(qz, t.z, t.w);
                k = fmaf(qx, t.x, k);
                k = fmaf(qy, t.y, k);
                best = fminf(best, k);
            }
            r += 8;
            float dx = db[r].x - mxq;               // in -2x space
            rdone = (dx * dx >= 4.0f * (best + p2)) || (r >= PAD + NPTS);
        }
        if (!ldone) {
#pragma unroll
            for (int u = 0; u < 8; u++) {
                float4 t = db[l - u];
                float k = fmaf(qz, t.z, t.w);
                k = fmaf(qx, t.x, k);
                k = fmaf(qy, t.y, k);
                best = fminf(best, k);
            }
            l -= 8;
            float dx = db[l].x - mxq;
            ldone = (dx * dx >= 4.0f * (best + p2)) || (l < PAD);
        }
    }

    // Per-thread partials.
    float sl, cx, cy, cz;
    {
        float d2 = fmaxf(best + p2, 0.0f);
        if (d2 < 0.98f) {
            // Exact: d2<1 forces every per-coord |diff|<1, so the summed
            // smooth_l1 over coords equals 0.5*d2 exactly.
            sl = 0.5f * d2;
        } else {
            // Cold exact fallback: full smem argmin + true smooth_l1.
            float bb = 3.4e38f;
            int bj = PAD;
            for (int j = 0; j < NPTS; j++) {
                float4 t = db[PAD + j];
                float k = fmaf(qz, t.z, t.w);
                k = fmaf(qx, t.x, k);
                k = fmaf(qy, t.y, k);
                if (k < bb) { bb = k; bj = PAD + j; }
            }
            float4 nb = db[bj];
            sl  = smooth_l1(qx, -0.5f * nb.x);
            sl += smooth_l1(qy, -0.5f * nb.y);
            sl += smooth_l1(qz, -0.5f * nb.z);
        }
        cx = qx; cy = qy; cz = qz;
    }

    // Deterministic block reduction (fixed tree order).
    red4[tid] = make_float4(sl, cx, cy, cz);
    __syncthreads();
    for (int s = TPB / 2; s > 0; s >>= 1) {
        if (tid < s) {
            float4 a = red4[tid];
            float4 b = red4[tid + s];
            red4[tid] = make_float4(a.x + b.x, a.y + b.y, a.z + b.z, a.w + b.w);
        }
        __syncthreads();
    }
    if (tid == 0) {
        float4 rr = red4[0];
        g_loss_part[blk]    = rr.x;
        g_cent_part[blk][0] = rr.y;
        g_cent_part[blk][1] = rr.z;
        g_cent_part[blk][2] = rr.w;
        __threadfence();
        unsigned int v = atomicAdd(&g_ctr, 1u);
        is_last = (v == NBLK - 1) ? 1u : 0u;
    }
    __syncthreads();

    // Last block finalizes (deterministic; counter self-resets for graph replay).
    if (is_last && tid < 32) {
        __threadfence();
        const int t = tid;
        float lp = 0.0f, lc = 0.0f;
        if (t < NSETS) {
            float s = 0.0f;
            for (int d = 0; d < 2; d++)
                for (int c = 0; c < CHUNKS; c++)
                    s += g_loss_part[(t * 2 + d) * CHUNKS + c];
            lp = s * (1.0f / (float)(NPTS * 3)) * w[t];

            float pc0 = 0, pc1 = 0, pc2 = 0, tc0 = 0, tc1 = 0, tc2 = 0;
            for (int c = 0; c < CHUNKS; c++) {
                int b0 = (t * 2 + 0) * CHUNKS + c;   // dir 0 queries = X_v
                int b1 = (t * 2 + 1) * CHUNKS + c;   // dir 1 queries = target
                pc0 += g_cent_part[b0][0]; pc1 += g_cent_part[b0][1]; pc2 += g_cent_part[b0][2];
                tc0 += g_cent_part[b1][0]; tc1 += g_cent_part[b1][1]; tc2 += g_cent_part[b1][2];
            }
            const float inv_n = 1.0f / (float)NPTS;
            lc += smooth_l1(pc0 * inv_n, tc0 * inv_n);
            lc += smooth_l1(pc1 * inv_n, tc1 * inv_n);
            lc += smooth_l1(pc2 * inv_n, tc2 * inv_n);
        }
#pragma unroll
        for (int o = 16; o > 0; o >>= 1) {
            lp += __shfl_down_sync(0xffffffff, lp, o);
            lc += __shfl_down_sync(0xffffffff, lc, o);
        }
        if (t == 0) {
            out[0] = lp * 0.5f;          // / B
            out[1] = lc * (1.0f / 6.0f); // / (B*3)
            g_ctr = 0;                   // reset for next graph replay
        }
    }
}

extern "C" void kernel_launch(void* const* d_in, const int* in_sizes, int n_in,
                              void* d_out, int out_size) {
    const float* Xv = (const float*)d_in[0];
    const float* Tv = (const float*)d_in[1];
    const float* w  = (const float*)d_in[2];
    float* out = (float*)d_out;

    sort_kernel<<<NSETS * 2, 256>>>(Xv, Tv);
    nn_kernel<<<NBLK, TPB>>>(w, out);
}